// round 14
// baseline (speedup 1.0000x reference)
#include <cuda_runtime.h>

// RNNModel: 2-layer tanh RNN, B=2048, T=512, I=5, H=64, O=1.
// R13: R10 champion + CORRECT pair rebalance. L1 warp offloads the k-low half
// of h1@W_ih1 AFTER publishing h1[t] (so the offload rides in L1's slack, not
// on L2's wait path). Producer/consumer sync via named-barrier arrive/sync
// split (bar.arrive non-blocking for producer, bar.sync for consumer; ~47cyc
// vs R12's mbarrier 90-150). h1 and P double-buffered -> 1 step of run-ahead.
//  L1: matvec1 -> store h1[t] -> k-low partial -> store P[t] -> arrive(full).
//      overwrite guard: sync(free[buf]) at t>=2.
//  L2: pre h2@W_hh1 (regs) -> sync(full) -> k-high + P combine -> arrive(free)
//      -> tanh -> store h2.
// Grid: 128 CTAs x 256 thr (4 pairs); 2 warps/SMSP.

#define BB 2048
#define TT 512

// shared float offsets
#define OFF_W1I 0        // W_ih1 [k2][ln] float4
#define OFF_H1  4096     // per pair 512: h1[2][4][64]
#define OFF_H2  6144     // per pair 256: h2[4][64]
#define OFF_P   7168     // per pair 1024: P[2][4][32] ulonglong2
#define SMEM_FLOATS 11264
#define SMEM_BYTES (SMEM_FLOATS*4)

typedef unsigned long long ull;

__device__ __forceinline__ void fma2(ull &a, ull b, ull c){
    asm("fma.rn.f32x2 %0, %1, %2, %0;" : "+l"(a) : "l"(b), "l"(c));
}
__device__ __forceinline__ ull add2(ull a, ull b){
    ull r; asm("add.rn.f32x2 %0, %1, %2;" : "=l"(r) : "l"(a), "l"(b)); return r;
}
__device__ __forceinline__ ull pack2(float lo, float hi){
    ull r; asm("mov.b64 %0, {%1, %2};" : "=l"(r) : "f"(lo), "f"(hi)); return r;
}
__device__ __forceinline__ void unpk(ull a, float &lo, float &hi){
    asm("mov.b64 {%0, %1}, %2;" : "=f"(lo), "=f"(hi) : "l"(a));
}
__device__ __forceinline__ float fast_tanh(float x){
    float e;
    asm("ex2.approx.f32 %0, %1;" : "=f"(e) : "f"(x * 2.8853900817779268f));
    float r;
    asm("rcp.approx.f32 %0, %1;" : "=f"(r) : "f"(e + 1.0f));
    return fmaf(-2.0f, r, 1.0f);
}
__device__ __forceinline__ void bar_sync64(int id){
    asm volatile("bar.sync %0, 64;" :: "r"(id) : "memory");
}
__device__ __forceinline__ void bar_arrive64(int id){
    asm volatile("bar.arrive %0, 64;" :: "r"(id) : "memory");
}

__global__ void __launch_bounds__(256, 1) rnn_r13_kernel(
    const float* __restrict__ x,
    const float* __restrict__ W_ih0, const float* __restrict__ W_hh0,
    const float* __restrict__ b_ih0, const float* __restrict__ b_hh0,
    const float* __restrict__ W_ih1, const float* __restrict__ W_hh1,
    const float* __restrict__ b_ih1, const float* __restrict__ b_hh1,
    const float* __restrict__ fc_W,  const float* __restrict__ fc_b,
    float* __restrict__ out)
{
    extern __shared__ float sm[];
    const int tid  = threadIdx.x;
    const int wid  = tid >> 5;
    const int ln   = tid & 31;
    const int pair = wid & 3;
    // named barriers per pair: full[buf] = 4*pair+buf, free[buf] = 4*pair+2+buf
    const int bFull0 = pair*4, bFull1 = pair*4+1, bFree0 = pair*4+2, bFree1 = pair*4+3;

    for (int idx = tid; idx < 1024; idx += 256){
        int k2 = idx >> 5, l = idx & 31, k = k2 * 2;
        ((float4*)(sm + OFF_W1I))[idx] =
            make_float4(W_ih1[l*64+k], W_ih1[l*64+k+1], W_ih1[(l+32)*64+k], W_ih1[(l+32)*64+k+1]);
    }
    for (int idx = tid; idx < 3072; idx += 256) sm[OFF_H1 + idx] = 0.0f;
    __syncthreads();

    const int r0  = blockIdx.x * 16 + pair * 4;
    float* h1b = sm + OFF_H1 + pair * 512;                   // [2][4][64]
    float* h2  = sm + OFF_H2 + pair * 256;                   // [4][64]
    ulonglong2* Pb = (ulonglong2*)(sm + OFF_P) + pair * 256; // [2][4][32]
    const ulonglong2* WIp = (const ulonglong2*)(sm + OFF_W1I) + ln;

    if (wid < 4){
        // ================= layer-1 warp (producer, runs ahead) =================
        ull Ra[32], Rb[32];                   // W_hh0 rows ln, ln+32
        {
            const ull* Wp = (const ull*)W_hh0;
            #pragma unroll
            for (int q = 0; q < 32; q++){
                Ra[q] = __ldg(Wp + ln*32 + q);
                Rb[q] = __ldg(Wp + (ln+32)*32 + q);
            }
        }
        float wa[5], wb[5];
        #pragma unroll
        for (int i = 0; i < 5; i++){
            wa[i] = W_ih0[ln*5 + i];
            wb[i] = W_ih0[(ln+32)*5 + i];
        }
        const float b0a = b_ih0[ln]    + b_hh0[ln];
        const float b0b = b_ih0[ln+32] + b_hh0[ln+32];

        float4 xq[4]; float xs[4];
        #pragma unroll
        for (int r = 0; r < 4; r++){
            const float* xr = x + (size_t)(r0 + r) * (TT*5);
            xq[r] = make_float4(__ldg(xr), __ldg(xr+1), __ldg(xr+2), __ldg(xr+3));
            xs[r] = __ldg(xr+4);
        }

        for (int t = 0; t < TT; t++){
            const float* hsrc = h1b + ((t+1)&1)*256;   // h1[t-1]
            float*       hdst = h1b + (t&1)*256;       // h1[t]

            float sxa[4], sxb[4];
            #pragma unroll
            for (int r = 0; r < 4; r++){
                float4 xv = xq[r]; float x4 = xs[r];
                float sa = fmaf(xv.x, wa[0], b0a), sb = fmaf(xv.x, wb[0], b0b);
                sa = fmaf(xv.y, wa[1], sa); sb = fmaf(xv.y, wb[1], sb);
                sa = fmaf(xv.z, wa[2], sa); sb = fmaf(xv.z, wb[2], sb);
                sa = fmaf(xv.w, wa[3], sa); sb = fmaf(xv.w, wb[3], sb);
                sa = fmaf(x4,   wa[4], sa); sb = fmaf(x4,   wb[4], sb);
                sxa[r] = sa; sxb[r] = sb;
            }
            if (t + 1 < TT){
                #pragma unroll
                for (int r = 0; r < 4; r++){
                    const float* xr = x + (size_t)(r0 + r) * (TT*5) + (t+1)*5;
                    xq[r] = make_float4(__ldg(xr), __ldg(xr+1), __ldg(xr+2), __ldg(xr+3));
                    xs[r] = __ldg(xr+4);
                }
            }

            // h1[t-1] @ W_hh0^T (W in regs, h pipelined depth-1)
            ull aA[4], aB[4];
            #pragma unroll
            for (int r = 0; r < 4; r++){ aA[r] = 0; aB[r] = 0; }
            {
                ulonglong2 c0 = *(const ulonglong2*)(hsrc +   0);
                ulonglong2 c1 = *(const ulonglong2*)(hsrc +  64);
                ulonglong2 c2 = *(const ulonglong2*)(hsrc + 128);
                ulonglong2 c3 = *(const ulonglong2*)(hsrc + 192);
                #pragma unroll
                for (int q = 0; q < 16; q++){
                    const int kn = (q < 15) ? q + 1 : 15;
                    ulonglong2 n0 = *(const ulonglong2*)(hsrc +   0 + kn*4);
                    ulonglong2 n1 = *(const ulonglong2*)(hsrc +  64 + kn*4);
                    ulonglong2 n2 = *(const ulonglong2*)(hsrc + 128 + kn*4);
                    ulonglong2 n3 = *(const ulonglong2*)(hsrc + 192 + kn*4);
                    fma2(aA[0],Ra[2*q],c0.x); fma2(aB[0],Rb[2*q],c0.x); fma2(aA[0],Ra[2*q+1],c0.y); fma2(aB[0],Rb[2*q+1],c0.y);
                    fma2(aA[1],Ra[2*q],c1.x); fma2(aB[1],Rb[2*q],c1.x); fma2(aA[1],Ra[2*q+1],c1.y); fma2(aB[1],Rb[2*q+1],c1.y);
                    fma2(aA[2],Ra[2*q],c2.x); fma2(aB[2],Rb[2*q],c2.x); fma2(aA[2],Ra[2*q+1],c2.y); fma2(aB[2],Rb[2*q+1],c2.y);
                    fma2(aA[3],Ra[2*q],c3.x); fma2(aB[3],Rb[2*q],c3.x); fma2(aA[3],Ra[2*q+1],c3.y); fma2(aB[3],Rb[2*q+1],c3.y);
                    c0 = n0; c1 = n1; c2 = n2; c3 = n3;
                }
            }

            // guard: L2 must be done with h1[t-2]/P[t-2] in this buffer
            if (t >= 2) bar_sync64((t & 1) ? bFree1 : bFree0);

            #pragma unroll
            for (int r = 0; r < 4; r++){
                float lo, hi;
                unpk(aA[r], lo, hi); float u = fast_tanh(lo + hi + sxa[r]);
                unpk(aB[r], lo, hi); float v = fast_tanh(lo + hi + sxb[r]);
                hdst[r*64 + ln]      = u;
                hdst[r*64 + ln + 32] = v;
            }
            __syncwarp();                     // h1[t] visible within own warp

            // k-low half of h1[t] @ W_ih1^T -> P[t] (rides in L1's slack)
            #pragma unroll
            for (int r = 0; r < 4; r++){ aA[r] = 0; aB[r] = 0; }
            #pragma unroll
            for (int q = 0; q < 8; q++){
                ulonglong2 w0 = WIp[(2*q  )*32];
                ulonglong2 w1 = WIp[(2*q+1)*32];
                ulonglong2 e0 = *(const ulonglong2*)(hdst +   0 + q*4);
                ulonglong2 e1 = *(const ulonglong2*)(hdst +  64 + q*4);
                ulonglong2 e2 = *(const ulonglong2*)(hdst + 128 + q*4);
                ulonglong2 e3 = *(const ulonglong2*)(hdst + 192 + q*4);
                fma2(aA[0],w0.x,e0.x); fma2(aB[0],w0.y,e0.x); fma2(aA[0],w1.x,e0.y); fma2(aB[0],w1.y,e0.y);
                fma2(aA[1],w0.x,e1.x); fma2(aB[1],w0.y,e1.x); fma2(aA[1],w1.x,e1.y); fma2(aB[1],w1.y,e1.y);
                fma2(aA[2],w0.x,e2.x); fma2(aB[2],w0.y,e2.x); fma2(aA[2],w1.x,e2.y); fma2(aB[2],w1.y,e2.y);
                fma2(aA[3],w0.x,e3.x); fma2(aB[3],w0.y,e3.x); fma2(aA[3],w1.x,e3.y); fma2(aB[3],w1.y,e3.y);
            }
            {
                ulonglong2* P = Pb + (t&1)*128;
                #pragma unroll
                for (int r = 0; r < 4; r++)
                    P[r*32 + ln] = make_ulonglong2(aA[r], aB[r]);
            }
            bar_arrive64((t & 1) ? bFull1 : bFull0);   // publish h1[t] + P[t]; non-blocking
        }
    } else {
        // ================= layer-2 warp (consumer) =================
        ull Ra[32], Rb[32];                   // W_hh1 rows ln, ln+32
        {
            const ull* Wp = (const ull*)W_hh1;
            #pragma unroll
            for (int q = 0; q < 32; q++){
                Ra[q] = __ldg(Wp + ln*32 + q);
                Rb[q] = __ldg(Wp + (ln+32)*32 + q);
            }
        }
        const float b1a = b_ih1[ln]    + b_hh1[ln];
        const float b1b = b_ih1[ln+32] + b_hh1[ln+32];

        float ta[4], tb[4];
        #pragma unroll
        for (int r = 0; r < 4; r++){ ta[r] = 0.f; tb[r] = 0.f; }

        for (int t = 0; t < TT; t++){
            // ---- pre-sync: bias + h2[t-1] @ W_hh1^T (regs, h2 pipelined) ----
            ull pA[4], pB[4];
            #pragma unroll
            for (int r = 0; r < 4; r++){ pA[r] = pack2(b1a, 0.f); pB[r] = pack2(b1b, 0.f); }
            {
                ulonglong2 g0 = *(const ulonglong2*)(h2 +   0);
                ulonglong2 g1 = *(const ulonglong2*)(h2 +  64);
                ulonglong2 g2 = *(const ulonglong2*)(h2 + 128);
                ulonglong2 g3 = *(const ulonglong2*)(h2 + 192);
                #pragma unroll
                for (int q = 0; q < 16; q++){
                    const int kn = (q < 15) ? q + 1 : 15;
                    ulonglong2 n0 = *(const ulonglong2*)(h2 +   0 + kn*4);
                    ulonglong2 n1 = *(const ulonglong2*)(h2 +  64 + kn*4);
                    ulonglong2 n2 = *(const ulonglong2*)(h2 + 128 + kn*4);
                    ulonglong2 n3 = *(const ulonglong2*)(h2 + 192 + kn*4);
                    fma2(pA[0],Ra[2*q],g0.x); fma2(pB[0],Rb[2*q],g0.x); fma2(pA[0],Ra[2*q+1],g0.y); fma2(pB[0],Rb[2*q+1],g0.y);
                    fma2(pA[1],Ra[2*q],g1.x); fma2(pB[1],Rb[2*q],g1.x); fma2(pA[1],Ra[2*q+1],g1.y); fma2(pB[1],Rb[2*q+1],g1.y);
                    fma2(pA[2],Ra[2*q],g2.x); fma2(pB[2],Rb[2*q],g2.x); fma2(pA[2],Ra[2*q+1],g2.y); fma2(pB[2],Rb[2*q+1],g2.y);
                    fma2(pA[3],Ra[2*q],g3.x); fma2(pB[3],Rb[2*q],g3.x); fma2(pA[3],Ra[2*q+1],g3.y); fma2(pB[3],Rb[2*q+1],g3.y);
                    g0 = n0; g1 = n1; g2 = n2; g3 = n3;
                }
            }

            bar_sync64((t & 1) ? bFull1 : bFull0);     // h1[t] + P[t] ready
            const float* hsrc = h1b + (t&1)*256;

            // ---- k-high half of h1[t] @ W_ih1^T + P combine ----
            #pragma unroll
            for (int q = 8; q < 16; q++){
                ulonglong2 w0 = WIp[(2*q  )*32];
                ulonglong2 w1 = WIp[(2*q+1)*32];
                ulonglong2 e0 = *(const ulonglong2*)(hsrc +   0 + q*4);
                ulonglong2 e1 = *(const ulonglong2*)(hsrc +  64 + q*4);
                ulonglong2 e2 = *(const ulonglong2*)(hsrc + 128 + q*4);
                ulonglong2 e3 = *(const ulonglong2*)(hsrc + 192 + q*4);
                fma2(pA[0],w0.x,e0.x); fma2(pB[0],w0.y,e0.x); fma2(pA[0],w1.x,e0.y); fma2(pB[0],w1.y,e0.y);
                fma2(pA[1],w0.x,e1.x); fma2(pB[1],w0.y,e1.x); fma2(pA[1],w1.x,e1.y); fma2(pB[1],w1.y,e1.y);
                fma2(pA[2],w0.x,e2.x); fma2(pB[2],w0.y,e2.x); fma2(pA[2],w1.x,e2.y); fma2(pB[2],w1.y,e2.y);
                fma2(pA[3],w0.x,e3.x); fma2(pB[3],w0.y,e3.x); fma2(pA[3],w1.x,e3.y); fma2(pB[3],w1.y,e3.y);
            }
            ull sA[4], sB[4];
            {
                const ulonglong2* P = Pb + (t&1)*128;
                #pragma unroll
                for (int r = 0; r < 4; r++){
                    ulonglong2 p1 = P[r*32 + ln];
                    sA[r] = add2(pA[r], p1.x);
                    sB[r] = add2(pB[r], p1.y);
                }
            }
            bar_arrive64((t & 1) ? bFree1 : bFree0);   // done reading h1[t] + P[t]

            #pragma unroll
            for (int r = 0; r < 4; r++){
                float lo, hi;
                unpk(sA[r], lo, hi); ta[r] = fast_tanh(lo + hi);
                unpk(sB[r], lo, hi); tb[r] = fast_tanh(lo + hi);
            }
            #pragma unroll
            for (int r = 0; r < 4; r++){
                h2[r*64 + ln]      = ta[r];
                h2[r*64 + ln + 32] = tb[r];
            }
            __syncwarp();                              // h2[t] visible next period
        }

        // ---- fc for this pair's 4 rows ----
        const float fa = fc_W[ln], fb = fc_W[ln+32];
        #pragma unroll
        for (int r = 0; r < 4; r++){
            float p = ta[r]*fa + tb[r]*fb;
            #pragma unroll
            for (int o = 16; o; o >>= 1)
                p += __shfl_xor_sync(0xffffffffu, p, o);
            if (ln == 0) out[r0 + r] = p + fc_b[0];
        }
    }
}

extern "C" void kernel_launch(void* const* d_in, const int* in_sizes, int n_in,
                              void* d_out, int out_size)
{
    const float* x     = (const float*)d_in[0];
    const float* W_ih0 = (const float*)d_in[1];
    const float* W_hh0 = (const float*)d_in[2];
    const float* b_ih0 = (const float*)d_in[3];
    const float* b_hh0 = (const float*)d_in[4];
    const float* W_ih1 = (const float*)d_in[5];
    const float* W_hh1 = (const float*)d_in[6];
    const float* b_ih1 = (const float*)d_in[7];
    const float* b_hh1 = (const float*)d_in[8];
    const float* fc_W  = (const float*)d_in[9];
    const float* fc_b  = (const float*)d_in[10];
    float* out = (float*)d_out;

    rnn_r13_kernel<<<BB / 16, 256, SMEM_BYTES>>>(
        x, W_ih0, W_hh0, b_ih0, b_hh0, W_ih1, W_hh1, b_ih1, b_hh1, fc_W, fc_b, out);
}

// round 15
// speedup vs baseline: 1.0905x; 1.0905x over previous
#include <cuda_runtime.h>

// RNNModel: 2-layer tanh RNN, B=2048, T=512, I=5, H=64, O=1.
// R14: R10 champion structure (warp-pair, W_hh0/W_hh1 in regs, W_ih1 smem,
// one bar.sync(64)/period) + strict micro-trims:
//  - x LDGs issued at step top, consumed post-matvec (latency hidden, no
//    cross-step prefetch liveness)
//  - hidden state stored interleaved (h[j], h[j+32]) -> one STS.64 per row
//    per lane; weight packing re-paired (k, k+32) to match, fma2 loops
//    unchanged
// Grid: 128 CTAs x 256 thr (4 pairs); 2 warps/SMSP.

#define BB 2048
#define TT 512

// shared float offsets
#define OFF_W1I 0        // W_ih1 [u][ln] float4 = (W[l][u],W[l][u+32],W[l+32][u],W[l+32][u+32])
#define OFF_H1  4096     // per pair 512: h1[2][4][64]  (interleaved pairs)
#define OFF_H2  6144     // per pair 256: h2[4][64]     (interleaved pairs)
#define SMEM_FLOATS 7168
#define SMEM_BYTES (SMEM_FLOATS*4)

typedef unsigned long long ull;

__device__ __forceinline__ void fma2(ull &a, ull b, ull c){
    asm("fma.rn.f32x2 %0, %1, %2, %0;" : "+l"(a) : "l"(b), "l"(c));
}
__device__ __forceinline__ ull pack2(float lo, float hi){
    ull r; asm("mov.b64 %0, {%1, %2};" : "=l"(r) : "f"(lo), "f"(hi)); return r;
}
__device__ __forceinline__ void unpk(ull a, float &lo, float &hi){
    asm("mov.b64 {%0, %1}, %2;" : "=f"(lo), "=f"(hi) : "l"(a));
}
__device__ __forceinline__ float fast_tanh(float x){
    float e;
    asm("ex2.approx.f32 %0, %1;" : "=f"(e) : "f"(x * 2.8853900817779268f));
    float r;
    asm("rcp.approx.f32 %0, %1;" : "=f"(r) : "f"(e + 1.0f));
    return fmaf(-2.0f, r, 1.0f);
}
__device__ __forceinline__ void barp(int id){
    asm volatile("bar.sync %0, 64;" :: "r"(id) : "memory");
}

__global__ void __launch_bounds__(256, 1) rnn_r14_kernel(
    const float* __restrict__ x,
    const float* __restrict__ W_ih0, const float* __restrict__ W_hh0,
    const float* __restrict__ b_ih0, const float* __restrict__ b_hh0,
    const float* __restrict__ W_ih1, const float* __restrict__ W_hh1,
    const float* __restrict__ b_ih1, const float* __restrict__ b_hh1,
    const float* __restrict__ fc_W,  const float* __restrict__ fc_b,
    float* __restrict__ out)
{
    extern __shared__ float sm[];
    const int tid  = threadIdx.x;
    const int wid  = tid >> 5;
    const int ln   = tid & 31;
    const int pair = wid & 3;
    const int bid  = pair + 1;

    // W_ih1 smem pack, pairs (u, u+32): float4[u][l] =
    //   (W[l][u], W[l][u+32], W[l+32][u], W[l+32][u+32])
    for (int idx = tid; idx < 1024; idx += 256){
        int u = idx >> 5, l = idx & 31;
        ((float4*)(sm + OFF_W1I))[idx] =
            make_float4(W_ih1[l*64+u], W_ih1[l*64+u+32], W_ih1[(l+32)*64+u], W_ih1[(l+32)*64+u+32]);
    }
    for (int idx = tid; idx < 3072; idx += 256) sm[OFF_H1 + idx] = 0.0f;
    __syncthreads();

    const int r0  = blockIdx.x * 16 + pair * 4;
    float* h1b = sm + OFF_H1 + pair * 512;   // [2][4][64]
    float* h2  = sm + OFF_H2 + pair * 256;   // [4][64]

    if (wid < 4){
        // ================= layer-1 warp =================
        // W_hh0 rows ln, ln+32 in regs, paired (u, u+32)
        ull Ra[32], Rb[32];
        #pragma unroll
        for (int u = 0; u < 32; u++){
            Ra[u] = pack2(__ldg(W_hh0 + ln*64 + u),      __ldg(W_hh0 + ln*64 + u + 32));
            Rb[u] = pack2(__ldg(W_hh0 + (ln+32)*64 + u), __ldg(W_hh0 + (ln+32)*64 + u + 32));
        }
        float wa[5], wb[5];
        #pragma unroll
        for (int i = 0; i < 5; i++){
            wa[i] = W_ih0[ln*5 + i];
            wb[i] = W_ih0[(ln+32)*5 + i];
        }
        const float b0a = b_ih0[ln]    + b_hh0[ln];
        const float b0b = b_ih0[ln+32] + b_hh0[ln+32];

        for (int t = 0; t < TT; t++){
            const float* hsrc = h1b + ((t+1)&1)*256;   // h1[t-1]
            float*       hdst = h1b + (t&1)*256;       // h1[t]

            // issue x loads for THIS step now; consume after the matvec
            float4 xq[4]; float xs[4];
            #pragma unroll
            for (int r = 0; r < 4; r++){
                const float* xr = x + (size_t)(r0 + r) * (TT*5) + t*5;
                xq[r] = make_float4(__ldg(xr), __ldg(xr+1), __ldg(xr+2), __ldg(xr+3));
                xs[r] = __ldg(xr+4);
            }

            // h1[t-1] @ W_hh0^T (W in regs, h pipelined depth-1)
            ull aA[4], aB[4];
            #pragma unroll
            for (int r = 0; r < 4; r++){ aA[r] = 0; aB[r] = 0; }
            {
                ulonglong2 c0 = *(const ulonglong2*)(hsrc +   0);
                ulonglong2 c1 = *(const ulonglong2*)(hsrc +  64);
                ulonglong2 c2 = *(const ulonglong2*)(hsrc + 128);
                ulonglong2 c3 = *(const ulonglong2*)(hsrc + 192);
                #pragma unroll
                for (int q = 0; q < 16; q++){
                    const int kn = (q < 15) ? q + 1 : 15;
                    ulonglong2 n0 = *(const ulonglong2*)(hsrc +   0 + kn*4);
                    ulonglong2 n1 = *(const ulonglong2*)(hsrc +  64 + kn*4);
                    ulonglong2 n2 = *(const ulonglong2*)(hsrc + 128 + kn*4);
                    ulonglong2 n3 = *(const ulonglong2*)(hsrc + 192 + kn*4);
                    fma2(aA[0],Ra[2*q],c0.x); fma2(aB[0],Rb[2*q],c0.x); fma2(aA[0],Ra[2*q+1],c0.y); fma2(aB[0],Rb[2*q+1],c0.y);
                    fma2(aA[1],Ra[2*q],c1.x); fma2(aB[1],Rb[2*q],c1.x); fma2(aA[1],Ra[2*q+1],c1.y); fma2(aB[1],Rb[2*q+1],c1.y);
                    fma2(aA[2],Ra[2*q],c2.x); fma2(aB[2],Rb[2*q],c2.x); fma2(aA[2],Ra[2*q+1],c2.y); fma2(aB[2],Rb[2*q+1],c2.y);
                    fma2(aA[3],Ra[2*q],c3.x); fma2(aB[3],Rb[2*q],c3.x); fma2(aA[3],Ra[2*q+1],c3.y); fma2(aB[3],Rb[2*q+1],c3.y);
                    c0 = n0; c1 = n1; c2 = n2; c3 = n3;
                }
            }
            // x projection (loads issued ~600 cyc ago — latency hidden)
            #pragma unroll
            for (int r = 0; r < 4; r++){
                float4 xv = xq[r]; float x4 = xs[r];
                float sa = fmaf(xv.x, wa[0], b0a), sb = fmaf(xv.x, wb[0], b0b);
                sa = fmaf(xv.y, wa[1], sa); sb = fmaf(xv.y, wb[1], sb);
                sa = fmaf(xv.z, wa[2], sa); sb = fmaf(xv.z, wb[2], sb);
                sa = fmaf(xv.w, wa[3], sa); sb = fmaf(xv.w, wb[3], sb);
                sa = fmaf(x4,   wa[4], sa); sb = fmaf(x4,   wb[4], sb);
                float lo, hi;
                unpk(aA[r], lo, hi); float u = fast_tanh(lo + hi + sa);
                unpk(aB[r], lo, hi); float v = fast_tanh(lo + hi + sb);
                *(ull*)(hdst + r*64 + 2*ln) = pack2(u, v);   // one STS.64
            }
            barp(bid);                        // h1[t] published (drains STS)
        }
    } else {
        // ================= layer-2 warp =================
        // W_hh1 rows ln, ln+32 in regs, paired (u, u+32)
        ull Ra[32], Rb[32];
        #pragma unroll
        for (int u = 0; u < 32; u++){
            Ra[u] = pack2(__ldg(W_hh1 + ln*64 + u),      __ldg(W_hh1 + ln*64 + u + 32));
            Rb[u] = pack2(__ldg(W_hh1 + (ln+32)*64 + u), __ldg(W_hh1 + (ln+32)*64 + u + 32));
        }
        const float b1a = b_ih1[ln]    + b_hh1[ln];
        const float b1b = b_ih1[ln+32] + b_hh1[ln+32];
        const ulonglong2* WIp = (const ulonglong2*)(sm + OFF_W1I) + ln;

        float ta[4], tb[4];
        #pragma unroll
        for (int r = 0; r < 4; r++){ ta[r] = 0.f; tb[r] = 0.f; }

        for (int t = 0; t < TT; t++){
            // ---- pre-barrier: bias + h2[t-1] @ W_hh1^T (regs, h2 pipelined) ----
            ull pA[4], pB[4];
            #pragma unroll
            for (int r = 0; r < 4; r++){ pA[r] = pack2(b1a, 0.f); pB[r] = pack2(b1b, 0.f); }
            {
                ulonglong2 g0 = *(const ulonglong2*)(h2 +   0);
                ulonglong2 g1 = *(const ulonglong2*)(h2 +  64);
                ulonglong2 g2 = *(const ulonglong2*)(h2 + 128);
                ulonglong2 g3 = *(const ulonglong2*)(h2 + 192);
                #pragma unroll
                for (int q = 0; q < 16; q++){
                    const int kn = (q < 15) ? q + 1 : 15;
                    ulonglong2 n0 = *(const ulonglong2*)(h2 +   0 + kn*4);
                    ulonglong2 n1 = *(const ulonglong2*)(h2 +  64 + kn*4);
                    ulonglong2 n2 = *(const ulonglong2*)(h2 + 128 + kn*4);
                    ulonglong2 n3 = *(const ulonglong2*)(h2 + 192 + kn*4);
                    fma2(pA[0],Ra[2*q],g0.x); fma2(pB[0],Rb[2*q],g0.x); fma2(pA[0],Ra[2*q+1],g0.y); fma2(pB[0],Rb[2*q+1],g0.y);
                    fma2(pA[1],Ra[2*q],g1.x); fma2(pB[1],Rb[2*q],g1.x); fma2(pA[1],Ra[2*q+1],g1.y); fma2(pB[1],Rb[2*q+1],g1.y);
                    fma2(pA[2],Ra[2*q],g2.x); fma2(pB[2],Rb[2*q],g2.x); fma2(pA[2],Ra[2*q+1],g2.y); fma2(pB[2],Rb[2*q+1],g2.y);
                    fma2(pA[3],Ra[2*q],g3.x); fma2(pB[3],Rb[2*q],g3.x); fma2(pA[3],Ra[2*q+1],g3.y); fma2(pB[3],Rb[2*q+1],g3.y);
                    g0 = n0; g1 = n1; g2 = n2; g3 = n3;
                }
            }

            barp(bid);                        // h1[t] ready
            const float* hsrc = h1b + (t&1)*256;

            // ---- post-barrier: + h1[t] @ W_ih1^T (smem W + h, both pipelined) ----
            {
                ulonglong2 w0 = WIp[0], w1 = WIp[32];
                ulonglong2 e0 = *(const ulonglong2*)(hsrc +   0);
                ulonglong2 e1 = *(const ulonglong2*)(hsrc +  64);
                ulonglong2 e2 = *(const ulonglong2*)(hsrc + 128);
                ulonglong2 e3 = *(const ulonglong2*)(hsrc + 192);
                #pragma unroll
                for (int q = 0; q < 16; q++){
                    const int kn = (q < 15) ? q + 1 : 15;
                    ulonglong2 m0 = WIp[(2*kn  )*32];
                    ulonglong2 m1 = WIp[(2*kn+1)*32];
                    ulonglong2 f0 = *(const ulonglong2*)(hsrc +   0 + kn*4);
                    ulonglong2 f1 = *(const ulonglong2*)(hsrc +  64 + kn*4);
                    ulonglong2 f2 = *(const ulonglong2*)(hsrc + 128 + kn*4);
                    ulonglong2 f3 = *(const ulonglong2*)(hsrc + 192 + kn*4);
                    fma2(pA[0],w0.x,e0.x); fma2(pB[0],w0.y,e0.x); fma2(pA[0],w1.x,e0.y); fma2(pB[0],w1.y,e0.y);
                    fma2(pA[1],w0.x,e1.x); fma2(pB[1],w0.y,e1.x); fma2(pA[1],w1.x,e1.y); fma2(pB[1],w1.y,e1.y);
                    fma2(pA[2],w0.x,e2.x); fma2(pB[2],w0.y,e2.x); fma2(pA[2],w1.x,e2.y); fma2(pB[2],w1.y,e2.y);
                    fma2(pA[3],w0.x,e3.x); fma2(pB[3],w0.y,e3.x); fma2(pA[3],w1.x,e3.y); fma2(pB[3],w1.y,e3.y);
                    w0 = m0; w1 = m1;
                    e0 = f0; e1 = f1; e2 = f2; e3 = f3;
                }
            }
            #pragma unroll
            for (int r = 0; r < 4; r++){
                float lo, hi;
                unpk(pA[r], lo, hi); ta[r] = fast_tanh(lo + hi);
                unpk(pB[r], lo, hi); tb[r] = fast_tanh(lo + hi);
                *(ull*)(h2 + r*64 + 2*ln) = pack2(ta[r], tb[r]);   // one STS.64
            }
            __syncwarp();                     // h2[t] visible for next pre-barrier phase
        }

        // ---- fc for this pair's 4 rows ----
        const float fa = fc_W[ln], fb = fc_W[ln+32];
        #pragma unroll
        for (int r = 0; r < 4; r++){
            float p = ta[r]*fa + tb[r]*fb;
            #pragma unroll
            for (int o = 16; o; o >>= 1)
                p += __shfl_xor_sync(0xffffffffu, p, o);
            if (ln == 0) out[r0 + r] = p + fc_b[0];
        }
    }
}

extern "C" void kernel_launch(void* const* d_in, const int* in_sizes, int n_in,
                              void* d_out, int out_size)
{
    const float* x     = (const float*)d_in[0];
    const float* W_ih0 = (const float*)d_in[1];
    const float* W_hh0 = (const float*)d_in[2];
    const float* b_ih0 = (const float*)d_in[3];
    const float* b_hh0 = (const float*)d_in[4];
    const float* W_ih1 = (const float*)d_in[5];
    const float* W_hh1 = (const float*)d_in[6];
    const float* b_ih1 = (const float*)d_in[7];
    const float* b_hh1 = (const float*)d_in[8];
    const float* fc_W  = (const float*)d_in[9];
    const float* fc_b  = (const float*)d_in[10];
    float* out = (float*)d_out;

    rnn_r14_kernel<<<BB / 16, 256, SMEM_BYTES>>>(
        x, W_ih0, W_hh0, b_ih0, b_hh0, W_ih1, W_hh1, b_ih1, b_hh1, fc_W, fc_b, out);
}